// round 16
// baseline (speedup 1.0000x reference)
#include <cuda_runtime.h>
#include <cuda_fp16.h>
#include <math.h>
#include <stdint.h>

// Problem constants (fixed by the reference setup)
#define BB   8
#define TT   1024
#define TEE  1024
#define HH   1024
#define NHH  8
#define DKK  128
#define MM   (BB * TT)       // 8192 rows
#define FF   4096            // FFN hidden

// ---------------------------------------------------------------------------
// Scratch (static device globals)
// ---------------------------------------------------------------------------
__device__ float  ws_x  [MM * HH];
__device__ float  ws_z  [MM * HH];
__device__ __half ws_qh [MM * HH];
__device__ __half ws_kh [MM * HH];
__device__ __half ws_vh [MM * HH];
__device__ __half ws_a  [MM * HH];   // fp16 A operand (LN out / ctx / enc)
__device__ __half ws_hid[MM * FF];   // fp16 FFN hidden
__device__ __half ws_b  [FF * HH];   // fp16 weight operand

// ---------------------------------------------------------------------------
// Helpers
// ---------------------------------------------------------------------------
// fp32 -> fp16 convert kernel: 4 floats/thread; n % 1024 == 0
__global__ __launch_bounds__(256)
void tohalf_kernel(const float* __restrict__ x, __half* __restrict__ y)
{
    const long long i = (long long)blockIdx.x * 256 + threadIdx.x;
    float4 v = ((const float4*)x)[i];
    __half2* o = (__half2*)(y + i * 4);
    o[0] = __floats2half2_rn(v.x, v.y);
    o[1] = __floats2half2_rn(v.z, v.w);
}

__device__ __forceinline__ void mma_f16(float* c, const uint32_t* a, const uint32_t* b) {
    asm volatile(
        "mma.sync.aligned.m16n8k16.row.col.f32.f16.f16.f32 "
        "{%0,%1,%2,%3},{%4,%5,%6,%7},{%8,%9},{%0,%1,%2,%3};"
        : "+f"(c[0]), "+f"(c[1]), "+f"(c[2]), "+f"(c[3])
        : "r"(a[0]), "r"(a[1]), "r"(a[2]), "r"(a[3]), "r"(b[0]), "r"(b[1]));
}

__device__ __forceinline__ void ldm_x4(uint32_t addr, uint32_t* r) {
    asm volatile("ldmatrix.sync.aligned.m8n8.x4.shared.b16 {%0,%1,%2,%3}, [%4];"
        : "=r"(r[0]), "=r"(r[1]), "=r"(r[2]), "=r"(r[3]) : "r"(addr));
}

__device__ __forceinline__ void cp_async16(uint32_t smem_addr, const void* gptr) {
    asm volatile("cp.async.cg.shared.global [%0], [%1], 16;"
                 :: "r"(smem_addr), "l"(gptr));
}

// ---------------------------------------------------------------------------
// fp16 tensor-core GEMM:  C = A[M,K] @ B[N,K]^T  (+ bias/relu/resid)
// K-chunk 64 (halved sync count vs R15), 2-stage cp.async.
// SROWH=72 halves (144 B rows: 16B-aligned; ldmatrix phases conflict-free:
// banks 4r mod 32). CTA tile 128x128, 8 warps, warp tile 64x32.
// Output: fp32 C or fp16 Ch. Requires: M,N % 128 == 0, K % 64 == 0.
// ---------------------------------------------------------------------------
#define SROWH 72                           // 64 data + 8 pad halves
#define PLANEH (128 * SROWH)               // 9216 halves
#define BUFH (2 * PLANEH)                  // A plane + B plane
#define GEMM_SMEM (2 * BUFH * 2)           // 73728 B

__global__ __launch_bounds__(256, 2)
void gemm_fp16_kernel(const __half* __restrict__ A,
                      const __half* __restrict__ B,
                      float* __restrict__ C,
                      __half* __restrict__ Ch,
                      int ldc, int M, int N, int K,
                      const float* __restrict__ bias,
                      const float* __restrict__ resid, int ldres,
                      int relu)
{
    extern __shared__ __half smh[];

    const int tid  = threadIdx.x;
    const int warp = tid >> 5;
    const int lane = tid & 31;
    const int wm = warp >> 2;
    const int wn = warp & 3;
    const int qr = lane >> 2;
    const int qc = lane & 3;
    const int m0 = blockIdx.y * 128;
    const int n0 = blockIdx.x * 128;

    const uint32_t sbase = (uint32_t)__cvta_generic_to_shared(smh);

    const int aRow = lane & 15;
    const int aKof = (lane >> 4) * 8;
    const int bRow = (lane >> 4) * 8 + (lane & 7);
    const int bKof = ((lane >> 3) & 1) * 8;

    float acc[4][4][4];
    #pragma unroll
    for (int mt = 0; mt < 4; ++mt)
        #pragma unroll
        for (int nt = 0; nt < 4; ++nt)
            #pragma unroll
            for (int r = 0; r < 4; ++r) acc[mt][nt][r] = 0.f;

    // copy: per plane 128 rows x 8 granules (16B = 8 halves); 2048 total, 8/thread
    auto issue = [&](int buf, int kk0) {
        #pragma unroll
        for (int i = 0; i < 8; ++i) {
            const int op   = i >> 2;                 // 0=A, 1=B
            const int widx = (i & 3) * 256 + tid;    // 0..1023
            const int row  = widx >> 3;
            const int g    = widx & 7;
            const __half* src = op
                ? B + (long long)(n0 + row) * K + kk0 + g * 8
                : A + (long long)(m0 + row) * K + kk0 + g * 8;
            const uint32_t soff = (uint32_t)((buf * BUFH + op * PLANEH + row * SROWH + g * 8) * 2);
            cp_async16(sbase + soff, src);
        }
        asm volatile("cp.async.commit_group;");
    };

    const int nchunks = K >> 6;

    issue(0, 0);
    asm volatile("cp.async.wait_group 0;");
    __syncthreads();

    for (int t = 0; t < nchunks; ++t) {
        const int buf = t & 1;
        if (t + 1 < nchunks) issue(buf ^ 1, (t + 1) * 64);

        const uint32_t bufH = (uint32_t)(buf * BUFH);

        #pragma unroll
        for (int ks = 0; ks < 4; ++ks) {
            const int k0 = ks * 16;
            uint32_t bf[2][4];
            #pragma unroll
            for (int p = 0; p < 2; ++p) {
                const uint32_t off = sbase +
                    (uint32_t)((bufH + PLANEH + (wn * 32 + p * 16 + bRow) * SROWH + k0 + bKof) * 2);
                ldm_x4(off, bf[p]);
            }
            #pragma unroll
            for (int mt = 0; mt < 4; ++mt) {
                uint32_t af[4];
                const uint32_t off = sbase +
                    (uint32_t)((bufH + (wm * 64 + mt * 16 + aRow) * SROWH + k0 + aKof) * 2);
                ldm_x4(off, af);
                #pragma unroll
                for (int nt = 0; nt < 4; ++nt)
                    mma_f16(acc[mt][nt], af, &bf[nt >> 1][(nt & 1) * 2]);
            }
        }

        if (t + 1 < nchunks) {
            asm volatile("cp.async.wait_group 0;");
            __syncthreads();
        }
    }

    #pragma unroll
    for (int mt = 0; mt < 4; ++mt) {
        const int row0 = m0 + wm * 64 + mt * 16 + qr;
        #pragma unroll
        for (int nt = 0; nt < 4; ++nt) {
            const int col = n0 + wn * 32 + nt * 8 + qc * 2;
            float2 v0 = make_float2(acc[mt][nt][0], acc[mt][nt][1]);
            float2 v1 = make_float2(acc[mt][nt][2], acc[mt][nt][3]);
            if (bias) {
                float2 b2 = *(const float2*)(bias + col);
                v0.x += b2.x; v0.y += b2.y;
                v1.x += b2.x; v1.y += b2.y;
            }
            if (relu) {
                v0.x = fmaxf(v0.x, 0.f); v0.y = fmaxf(v0.y, 0.f);
                v1.x = fmaxf(v1.x, 0.f); v1.y = fmaxf(v1.y, 0.f);
            }
            if (resid) {
                float2 r0 = *(const float2*)(resid + (long long)row0 * ldres + col);
                float2 r1 = *(const float2*)(resid + (long long)(row0 + 8) * ldres + col);
                v0.x += r0.x; v0.y += r0.y;
                v1.x += r1.x; v1.y += r1.y;
            }
            if (Ch) {
                *(__half2*)(Ch + (long long)row0 * ldc + col)       = __floats2half2_rn(v0.x, v0.y);
                *(__half2*)(Ch + (long long)(row0 + 8) * ldc + col) = __floats2half2_rn(v1.x, v1.y);
            } else {
                *(float2*)(C + (long long)row0 * ldc + col)       = v0;
                *(float2*)(C + (long long)(row0 + 8) * ldc + col) = v1;
            }
        }
    }
}

// ---------------------------------------------------------------------------
// fp16 tensor-core flash attention (DK=128). Q/K/V fp16 (written by QKV
// GEMMs); softmax in fp32; P stored fp16; O fp32 accumulators.
// BQ=128, 8 warps; warp w owns query rows w*16..+15 over the BK=32 key tile.
// smem (halves): Q prologue 4 planes x (128x40) = 20480; then
//   sK 4 planes x (32x40)=5120 | sVt 128x40=5120 | sP 128x40=5120.
// ---------------------------------------------------------------------------
#define FBQ 128
#define FBK 32
#define FROW 40                            // halves per 32-chunk row
#define KPL (32 * FROW)                    // 1280 halves per K plane
#define SVT_OFF (4 * KPL)                  // 5120
#define SP_OFF  (SVT_OFF + 128 * FROW)     // 10240
#define FLASH_SMEM (4 * 128 * FROW * 2)    // 40960 B (Q prologue is max)

__global__ __launch_bounds__(256)
void flash_f16_kernel(const __half* __restrict__ Qg, const __half* __restrict__ Kg,
                      const __half* __restrict__ Vg, __half* __restrict__ Og,
                      int Tk, int causal)
{
    extern __shared__ __half smf[];

    const int tid  = threadIdx.x;
    const int warp = tid >> 5;
    const int lane = tid & 31;
    const int qr = lane >> 2, qc = lane & 3;
    const int q0 = blockIdx.x * FBQ;
    const int bh = blockIdx.y;
    const int bb = bh >> 3, hh = bh & 7;

    const __half* Qp = Qg + ((long long)(bb * TT + q0)) * HH + hh * DKK;
    const __half* Kp = Kg + ((long long)bb * Tk) * HH + hh * DKK;
    const __half* Vp = Vg + ((long long)bb * Tk) * HH + hh * DKK;

    const uint32_t sbase = (uint32_t)__cvta_generic_to_shared(smf);

    // b16 fragment addressing (validated in the fp16 GEMM)
    const int aRow = lane & 15;
    const int aKof = (lane >> 4) * 8;
    const int bRow = (lane >> 4) * 8 + (lane & 7);
    const int bKof = ((lane >> 3) & 1) * 8;

    // ---- prologue: Q tile (128x128 halves) -> chunk planes -> registers ----
    #pragma unroll
    for (int j = 0; j < 8; ++j) {
        const int idx = j * 256 + tid;        // 2048 granules
        const int row = idx >> 4, g = idx & 15;
        *(uint4*)&smf[(g >> 2) * (128 * FROW) + row * FROW + (g & 3) * 8] =
            *(const uint4*)(Qp + (long long)row * HH + g * 8);
    }
    __syncthreads();
    uint32_t qf[8][4];
    #pragma unroll
    for (int ks = 0; ks < 8; ++ks) {
        const int pl = ks >> 1, k0 = (ks & 1) * 16;
        ldm_x4(sbase + (uint32_t)((pl * 128 * FROW + (warp * 16 + aRow) * FROW + k0 + aKof) * 2),
               qf[ks]);
    }
    __syncthreads();

    const float scale = 0.08838834764831845f;
    float o[16][4];
    #pragma unroll
    for (int nt = 0; nt < 16; ++nt) {
        o[nt][0] = 0.f; o[nt][1] = 0.f; o[nt][2] = 0.f; o[nt][3] = 0.f;
    }
    float m0 = -INFINITY, m1 = -INFINITY, l0 = 0.f, l1 = 0.f;

    const int nkt = causal ? (q0 / FBK + 4) : (Tk / FBK);

    for (int kt = 0; kt < nkt; ++kt) {
        // K tile (32x128 halves) -> 4 chunk planes (512 granules, 2/thread)
        #pragma unroll
        for (int j = 0; j < 2; ++j) {
            const int idx = j * 256 + tid;
            const int row = idx >> 4, g = idx & 15;
            *(uint4*)&smf[(g >> 2) * KPL + row * FROW + (g & 3) * 8] =
                *(const uint4*)(Kp + (long long)(kt * FBK + row) * HH + g * 8);
        }
        // V tile transposed -> sVt[d][k] (fp16)
        #pragma unroll
        for (int i = 0; i < 2; ++i) {
            const int db = i * 8 + warp;      // 0..15, 8 halves each
            const __half* vp = Vp + (long long)(kt * FBK + lane) * HH + db * 8;
            #pragma unroll
            for (int j = 0; j < 8; ++j)
                smf[SVT_OFF + (db * 8 + j) * FROW + lane] = vp[j];
        }
        __syncthreads();

        // ---- S = Q K^T (fp16 mma) ----
        float facc[4][4];
        #pragma unroll
        for (int nt = 0; nt < 4; ++nt) {
            facc[nt][0] = 0.f; facc[nt][1] = 0.f; facc[nt][2] = 0.f; facc[nt][3] = 0.f;
        }
        #pragma unroll
        for (int ks = 0; ks < 8; ++ks) {
            const int pl = ks >> 1, k0 = (ks & 1) * 16;
            uint32_t bf[2][4];
            #pragma unroll
            for (int p = 0; p < 2; ++p)
                ldm_x4(sbase + (uint32_t)((pl * KPL + (p * 16 + bRow) * FROW + k0 + bKof) * 2),
                       bf[p]);
            #pragma unroll
            for (int nt = 0; nt < 4; ++nt)
                mma_f16(facc[nt], qf[ks], &bf[nt >> 1][(nt & 1) * 2]);
        }

        // ---- scale + mask + online softmax (fp32) ----
        const int gq0 = q0 + warp * 16 + qr;
        const int gq1 = gq0 + 8;
        float mx0 = -INFINITY, mx1 = -INFINITY;
        #pragma unroll
        for (int nt = 0; nt < 4; ++nt) {
            const int kc0 = kt * FBK + nt * 8 + 2 * qc;
            facc[nt][0] *= scale; facc[nt][1] *= scale;
            facc[nt][2] *= scale; facc[nt][3] *= scale;
            if (causal) {
                if (kc0     > gq0) facc[nt][0] = -INFINITY;
                if (kc0 + 1 > gq0) facc[nt][1] = -INFINITY;
                if (kc0     > gq1) facc[nt][2] = -INFINITY;
                if (kc0 + 1 > gq1) facc[nt][3] = -INFINITY;
            }
            mx0 = fmaxf(mx0, fmaxf(facc[nt][0], facc[nt][1]));
            mx1 = fmaxf(mx1, fmaxf(facc[nt][2], facc[nt][3]));
        }
        mx0 = fmaxf(mx0, __shfl_xor_sync(0xffffffffu, mx0, 1));
        mx0 = fmaxf(mx0, __shfl_xor_sync(0xffffffffu, mx0, 2));
        mx1 = fmaxf(mx1, __shfl_xor_sync(0xffffffffu, mx1, 1));
        mx1 = fmaxf(mx1, __shfl_xor_sync(0xffffffffu, mx1, 2));
        const float mn0 = fmaxf(m0, mx0), mn1 = fmaxf(m1, mx1);
        const float corr0 = __expf(m0 - mn0), corr1 = __expf(m1 - mn1);

        float rs0 = 0.f, rs1 = 0.f;
        #pragma unroll
        for (int nt = 0; nt < 4; ++nt) {
            float p0 = __expf(facc[nt][0] - mn0), p1 = __expf(facc[nt][1] - mn0);
            float p2 = __expf(facc[nt][2] - mn1), p3 = __expf(facc[nt][3] - mn1);
            rs0 += p0 + p1; rs1 += p2 + p3;
            *(__half2*)&smf[SP_OFF + (warp * 16 + qr) * FROW + nt * 8 + 2 * qc] =
                __floats2half2_rn(p0, p1);
            *(__half2*)&smf[SP_OFF + (warp * 16 + qr + 8) * FROW + nt * 8 + 2 * qc] =
                __floats2half2_rn(p2, p3);
        }
        rs0 += __shfl_xor_sync(0xffffffffu, rs0, 1);
        rs0 += __shfl_xor_sync(0xffffffffu, rs0, 2);
        rs1 += __shfl_xor_sync(0xffffffffu, rs1, 1);
        rs1 += __shfl_xor_sync(0xffffffffu, rs1, 2);
        l0 = l0 * corr0 + rs0;  l1 = l1 * corr1 + rs1;
        m0 = mn0;  m1 = mn1;
        #pragma unroll
        for (int nt = 0; nt < 16; ++nt) {
            o[nt][0] *= corr0; o[nt][1] *= corr0;
            o[nt][2] *= corr1; o[nt][3] *= corr1;
        }
        __syncwarp();   // P region is warp-private

        // ---- O += P V (fp16 mma) ----
        #pragma unroll
        for (int ks = 0; ks < 2; ++ks) {
            const int k0 = ks * 16;
            uint32_t af[4];
            ldm_x4(sbase + (uint32_t)((SP_OFF + (warp * 16 + aRow) * FROW + k0 + aKof) * 2), af);
            #pragma unroll
            for (int p = 0; p < 8; ++p) {
                uint32_t bf[4];
                ldm_x4(sbase + (uint32_t)((SVT_OFF + (p * 16 + bRow) * FROW + k0 + bKof) * 2), bf);
                mma_f16(o[p * 2],     af, &bf[0]);
                mma_f16(o[p * 2 + 1], af, &bf[2]);
            }
        }
        __syncthreads();   // all warps done with sK/sVt before next overwrite
    }

    // ---- finalize + store ctx as fp16 ----
    const float inv0 = 1.f / l0, inv1 = 1.f / l1;
    const long long r0 = ((long long)(bb * TT + q0 + warp * 16 + qr)) * HH + hh * DKK;
    const long long r1 = r0 + 8LL * HH;
    #pragma unroll
    for (int nt = 0; nt < 16; ++nt) {
        const int d = nt * 8 + 2 * qc;
        *(__half2*)(Og + r0 + d) = __floats2half2_rn(o[nt][0] * inv0, o[nt][1] * inv0);
        *(__half2*)(Og + r1 + d) = __floats2half2_rn(o[nt][2] * inv1, o[nt][3] * inv1);
    }
}

// ---------------------------------------------------------------------------
// LayerNorm over last dim (1024); writes fp16 directly (GEMM operand).
// ---------------------------------------------------------------------------
__global__ __launch_bounds__(256)
void layernorm_half_kernel(const float* __restrict__ x, const float* __restrict__ g,
                           const float* __restrict__ b, __half* __restrict__ y)
{
    const long long row = blockIdx.x;
    const int tid = threadIdx.x;
    float4 v = ((const float4*)(x + row * HH))[tid];

    __shared__ float red[8];
    float s = v.x + v.y + v.z + v.w;
    #pragma unroll
    for (int o = 16; o; o >>= 1) s += __shfl_xor_sync(0xffffffffu, s, o);
    if ((tid & 31) == 0) red[tid >> 5] = s;
    __syncthreads();
    float mean = (red[0] + red[1] + red[2] + red[3] +
                  red[4] + red[5] + red[6] + red[7]) * (1.f / HH);
    __syncthreads();

    float dx = v.x - mean, dy = v.y - mean, dz = v.z - mean, dw = v.w - mean;
    float sq = dx * dx + dy * dy + dz * dz + dw * dw;
    #pragma unroll
    for (int o = 16; o; o >>= 1) sq += __shfl_xor_sync(0xffffffffu, sq, o);
    if ((tid & 31) == 0) red[tid >> 5] = sq;
    __syncthreads();
    float var = (red[0] + red[1] + red[2] + red[3] +
                 red[4] + red[5] + red[6] + red[7]) * (1.f / HH);
    float rstd = rsqrtf(var + 1e-5f);

    float4 g4 = ((const float4*)g)[tid];
    float4 b4 = ((const float4*)b)[tid];
    float y0 = dx * rstd * g4.x + b4.x;
    float y1 = dy * rstd * g4.y + b4.y;
    float y2 = dz * rstd * g4.z + b4.z;
    float y3 = dw * rstd * g4.w + b4.w;

    __half2* o = (__half2*)(y + row * HH + tid * 4);
    o[0] = __floats2half2_rn(y0, y1);
    o[1] = __floats2half2_rn(y2, y3);
}

// ---------------------------------------------------------------------------
// Host orchestration
// ---------------------------------------------------------------------------
extern "C" void kernel_launch(void* const* d_in, const int* in_sizes, int n_in,
                              void* d_out, int out_size)
{
    const float* input_ = (const float*)d_in[0];
    const float* enc    = (const float*)d_in[1];
    const float* Wq_s = (const float*)d_in[4];
    const float* Wk_s = (const float*)d_in[5];
    const float* Wv_s = (const float*)d_in[6];
    const float* Wo_s = (const float*)d_in[7];
    const float* Wq_c = (const float*)d_in[8];
    const float* Wk_c = (const float*)d_in[9];
    const float* Wv_c = (const float*)d_in[10];
    const float* Wo_c = (const float*)d_in[11];
    const float* w1   = (const float*)d_in[12];
    const float* b1   = (const float*)d_in[13];
    const float* w2   = (const float*)d_in[14];
    const float* b2   = (const float*)d_in[15];
    const float* g_mmha = (const float*)d_in[16];
    const float* b_mmha = (const float*)d_in[17];
    const float* g_mha  = (const float*)d_in[18];
    const float* b_mha  = (const float*)d_in[19];
    const float* g_ffn  = (const float*)d_in[20];
    const float* b_ffn  = (const float*)d_in[21];
    float* out = (float*)d_out;

    float *x, *z;
    __half *qh, *kh, *vh, *a, *hid, *bw;
    cudaGetSymbolAddress((void**)&x,   ws_x);
    cudaGetSymbolAddress((void**)&z,   ws_z);
    cudaGetSymbolAddress((void**)&qh,  ws_qh);
    cudaGetSymbolAddress((void**)&kh,  ws_kh);
    cudaGetSymbolAddress((void**)&vh,  ws_vh);
    cudaGetSymbolAddress((void**)&a,   ws_a);
    cudaGetSymbolAddress((void**)&hid, ws_hid);
    cudaGetSymbolAddress((void**)&bw,  ws_b);

    cudaFuncSetAttribute(flash_f16_kernel,
                         cudaFuncAttributeMaxDynamicSharedMemorySize, FLASH_SMEM);
    cudaFuncSetAttribute(gemm_fp16_kernel,
                         cudaFuncAttributeMaxDynamicSharedMemorySize, GEMM_SMEM);

    auto tohalf = [&](const float* src, __half* dst, long long n) {
        tohalf_kernel<<<(int)(n / 1024), 256>>>(src, dst);
    };
    auto gemm = [&](const __half* pA, float* C, __half* Ch, int M, int N, int K,
                    const float* bias, const float* resid, int relu) {
        dim3 grid(N / 128, M / 128, 1);
        gemm_fp16_kernel<<<grid, 256, GEMM_SMEM>>>(pA, bw, C, Ch, N, M, N, K,
                                                   bias, resid, N, relu);
    };
    auto flash = [&](const __half* Q, const __half* K, const __half* V, __half* O,
                     int Tk, int causal) {
        dim3 grid(TT / FBQ, BB * NHH);
        flash_f16_kernel<<<grid, 256, FLASH_SMEM>>>(Q, K, V, O, Tk, causal);
    };

    const long long nW  = (long long)HH * HH;
    const long long nW1 = (long long)FF * HH;
    const long long nMH = (long long)MM * HH;

    // ---- self attention ----
    layernorm_half_kernel<<<MM, 256>>>(input_, g_mmha, b_mmha, a);
    tohalf(Wq_s, bw, nW);  gemm(a, 0, qh, MM, HH, HH, nullptr, nullptr, 0);
    tohalf(Wk_s, bw, nW);  gemm(a, 0, kh, MM, HH, HH, nullptr, nullptr, 0);
    tohalf(Wv_s, bw, nW);  gemm(a, 0, vh, MM, HH, HH, nullptr, nullptr, 0);
    flash(qh, kh, vh, a, TT, /*causal=*/1);              // ctx (fp16) -> a
    tohalf(Wo_s, bw, nW);  gemm(a, x, 0, MM, HH, HH, nullptr, input_, 0);

    // ---- cross attention ----
    layernorm_half_kernel<<<MM, 256>>>(x, g_mha, b_mha, a);
    tohalf(Wq_c, bw, nW);  gemm(a, 0, qh, MM, HH, HH, nullptr, nullptr, 0);
    tohalf(enc, a, nMH);                                 // enc (fp16) -> a
    tohalf(Wk_c, bw, nW);  gemm(a, 0, kh, BB * TEE, HH, HH, nullptr, nullptr, 0);
    tohalf(Wv_c, bw, nW);  gemm(a, 0, vh, BB * TEE, HH, HH, nullptr, nullptr, 0);
    flash(qh, kh, vh, a, TEE, /*causal=*/0);
    tohalf(Wo_c, bw, nW);  gemm(a, z, 0, MM, HH, HH, nullptr, x, 0);

    // ---- FFN ----
    layernorm_half_kernel<<<MM, 256>>>(z, g_ffn, b_ffn, a);
    tohalf(w1, bw, nW1);   gemm(a, 0, hid, MM, FF, HH, b1, nullptr, 1);
    tohalf(w2, bw, nW1);   gemm(hid, out, 0, MM, HH, FF, b2, z, 0);
}